// round 5
// baseline (speedup 1.0000x reference)
#include <cuda_runtime.h>
#include <cuda_bf16.h>
#include <cstdint>
#include <cstddef>

// ---------------------------------------------------------------------------
// Problem constants
// ---------------------------------------------------------------------------
#define N_CODES 4880
#define T_STEPS 4096
#define VDIM    512
#define HD      512
#define G3      1536   // 3*HD

typedef unsigned long long ull;

// ---------------------------------------------------------------------------
// Scratch (device globals — no allocation allowed)
// ---------------------------------------------------------------------------
__device__ float g_visit[(size_t)T_STEPS * VDIM];     // 8 MB
__device__ float g_gi[(size_t)T_STEPS * G3];          // 24 MB
__device__ float g_hs[(size_t)T_STEPS * HD];          // 8 MB
__device__ float g_logits[T_STEPS];
__device__ float g_alpha[T_STEPS];
__device__ float g_part[32 * HD];
__device__ unsigned g1done[32];     // GEMM1 tiles finished per t-chunk (target 8)
__device__ unsigned g2done[32];     // GEMM2 tiles finished per t-chunk (target 24)

// ---------------------------------------------------------------------------
// Helpers
// ---------------------------------------------------------------------------
__device__ __forceinline__ unsigned smem_u32(const void* p) {
    unsigned a;
    asm("{ .reg .u64 t; cvta.to.shared.u64 t, %1; cvt.u32.u64 %0, t; }"
        : "=r"(a) : "l"(p));
    return a;
}
__device__ __forceinline__ unsigned mapa_u32(unsigned laddr, int rk) {
    unsigned r;
    asm("mapa.shared::cluster.u32 %0, %1, %2;" : "=r"(r) : "r"(laddr), "r"(rk));
    return r;
}
__device__ __forceinline__ ull pk2(float a, float b) {
    ull r; asm("mov.b64 %0, {%1, %2};" : "=l"(r) : "f"(a), "f"(b)); return r;
}
__device__ __forceinline__ ull pk2dup(float a) { return pk2(a, a); }
__device__ __forceinline__ void fma2(ull& d, ull a, ull b) {
    asm("fma.rn.f32x2 %0, %1, %2, %0;" : "+l"(d) : "l"(a), "l"(b));
}
__device__ __forceinline__ float2 upk2(ull v) {
    float2 r; asm("mov.b64 {%0, %1}, %2;" : "=f"(r.x), "=f"(r.y) : "l"(v));
    return r;
}
__device__ __forceinline__ float tanh_fast(float x) {
    float r; asm("tanh.approx.f32 %0, %1;" : "=f"(r) : "f"(x)); return r;
}
__device__ __forceinline__ void cluster_sync_all() {
    asm volatile("barrier.cluster.arrive.aligned;" ::: "memory");
    asm volatile("barrier.cluster.wait.aligned;" ::: "memory");
}
__device__ __forceinline__ void mbar_init(unsigned a, unsigned cnt) {
    asm volatile("mbarrier.init.shared.b64 [%0], %1;" :: "r"(a), "r"(cnt) : "memory");
}
__device__ __forceinline__ void mbar_expect(unsigned a, unsigned bytes) {
    asm volatile("mbarrier.arrive.expect_tx.shared.b64 _, [%0], %1;"
                 :: "r"(a), "r"(bytes) : "memory");
}
__device__ __forceinline__ void mbar_wait(unsigned a, unsigned parity) {
    asm volatile(
        "{\n\t.reg .pred P;\n\t"
        "LW_%=:\n\t"
        "mbarrier.try_wait.parity.acquire.cluster.shared::cta.b64 P, [%0], %1, 0x989680;\n\t"
        "@P bra.uni LD_%=;\n\t"
        "bra.uni LW_%=;\n\t"
        "LD_%=:\n\t}"
        :: "r"(a), "r"(parity) : "memory");
}
__device__ __forceinline__ void st_async_pre(unsigned ra, unsigned rb, unsigned val) {
    asm volatile(
        "st.async.shared::cluster.mbarrier::complete_tx::bytes.b32 [%0], %1, [%2];"
        :: "r"(ra), "r"(val), "r"(rb) : "memory");
}
__device__ __forceinline__ unsigned ld_acq(const unsigned* p) {
    unsigned v;
    asm volatile("ld.acquire.gpu.global.u32 %0, [%1];" : "=r"(v) : "l"(p));
    return v;
}

// ---------------------------------------------------------------------------
// Flag init (each replay)
// ---------------------------------------------------------------------------
__global__ void init_flags_kernel()
{
    if (threadIdx.x < 32) g1done[threadIdx.x] = 0u;
    else                  g2done[threadIdx.x - 32] = 0u;
}

// ---------------------------------------------------------------------------
// GEMM1 tile: visit[t0:t0+128][d0:d0+64] = H.T @ X  (k = 4880)
// ---------------------------------------------------------------------------
__device__ void gemm1_tile(const float* __restrict__ H, const float* __restrict__ X,
                           int bx, int by, char* dynsm)
{
    float* As = (float*)dynsm;            // 16x128
    float* Bs = As + 16 * 128;            // 16x64
    const int tid = threadIdx.x;
    const int t0 = bx * 128;
    const int d0 = by * 64;
    const int tx = tid & 15;
    const int ty = tid >> 4;

    ull acc2[4][4];
#pragma unroll
    for (int mp = 0; mp < 4; mp++)
#pragma unroll
        for (int n = 0; n < 4; n++) acc2[mp][n] = 0ull;

    for (int k0 = 0; k0 < N_CODES; k0 += 16) {
#pragma unroll
        for (int j = 0; j < 2; j++) {
            int idx = tid + (j << 8);
            int kk  = idx >> 5;
            int tt4 = (idx & 31) << 2;
            float4 v = *(const float4*)(H + (size_t)(k0 + kk) * T_STEPS + t0 + tt4);
            *(float4*)(As + (kk << 7) + tt4) = v;
        }
        {
            int kk  = tid >> 4;
            int dd4 = (tid & 15) << 2;
            float4 v = *(const float4*)(X + (size_t)(k0 + kk) * VDIM + d0 + dd4);
            *(float4*)(Bs + (kk << 6) + dd4) = v;
        }
        __syncthreads();
#pragma unroll
        for (int kk = 0; kk < 16; kk++) {
            const longlong2* ap = (const longlong2*)(As + (kk << 7) + (ty << 3));
            longlong2 a01 = ap[0];
            longlong2 a23 = ap[1];
            ull am[4] = {(ull)a01.x, (ull)a01.y, (ull)a23.x, (ull)a23.y};
            float4 b = *(const float4*)(Bs + (kk << 6) + (tx << 2));
            ull bd[4] = {pk2dup(b.x), pk2dup(b.y), pk2dup(b.z), pk2dup(b.w)};
#pragma unroll
            for (int mp = 0; mp < 4; mp++)
#pragma unroll
                for (int n = 0; n < 4; n++)
                    fma2(acc2[mp][n], am[mp], bd[n]);
        }
        __syncthreads();
    }
#pragma unroll
    for (int mp = 0; mp < 4; mp++) {
        float2 c0 = upk2(acc2[mp][0]);
        float2 c1 = upk2(acc2[mp][1]);
        float2 c2 = upk2(acc2[mp][2]);
        float2 c3 = upk2(acc2[mp][3]);
        size_t r0 = (size_t)(t0 + (ty << 3) + 2 * mp) * VDIM + d0 + (tx << 2);
        *(float4*)(g_visit + r0)        = make_float4(c0.x, c1.x, c2.x, c3.x);
        *(float4*)(g_visit + r0 + VDIM) = make_float4(c0.y, c1.y, c2.y, c3.y);
    }
}

// ---------------------------------------------------------------------------
// GEMM2 tile: gi[t0:t0+128][g0:g0+64] = visit @ W_ih.T + b_ih  (k = 512)
// ---------------------------------------------------------------------------
__device__ void gemm2_tile(const float* __restrict__ Wih, const float* __restrict__ bih,
                           int bx, int by, char* dynsm)
{
    float* As = (float*)dynsm;
    float* Bs = As + 16 * 128;
    const int tid = threadIdx.x;
    const int t0 = bx * 128;
    const int g0 = by * 64;
    const int tx = tid & 15;
    const int ty = tid >> 4;

    ull acc2[4][4];
#pragma unroll
    for (int mp = 0; mp < 4; mp++)
#pragma unroll
        for (int n = 0; n < 4; n++) acc2[mp][n] = 0ull;

    for (int k0 = 0; k0 < VDIM; k0 += 16) {
#pragma unroll
        for (int j = 0; j < 2; j++) {
            int idx = tid + (j << 8);
            int tt  = idx >> 2;
            int kk  = (idx & 3) << 2;
            float4 v = *(const float4*)(g_visit + (size_t)(t0 + tt) * VDIM + k0 + kk);
            As[(kk + 0) * 128 + tt] = v.x;
            As[(kk + 1) * 128 + tt] = v.y;
            As[(kk + 2) * 128 + tt] = v.z;
            As[(kk + 3) * 128 + tt] = v.w;
        }
        {
            int gg = tid >> 2;
            int kk = (tid & 3) << 2;
            float4 v = *(const float4*)(Wih + (size_t)(g0 + gg) * VDIM + k0 + kk);
            Bs[(kk + 0) * 64 + gg] = v.x;
            Bs[(kk + 1) * 64 + gg] = v.y;
            Bs[(kk + 2) * 64 + gg] = v.z;
            Bs[(kk + 3) * 64 + gg] = v.w;
        }
        __syncthreads();
#pragma unroll
        for (int kk = 0; kk < 16; kk++) {
            const longlong2* ap = (const longlong2*)(As + (kk << 7) + (ty << 3));
            longlong2 a01 = ap[0];
            longlong2 a23 = ap[1];
            ull am[4] = {(ull)a01.x, (ull)a01.y, (ull)a23.x, (ull)a23.y};
            float4 b = *(const float4*)(Bs + (kk << 6) + (tx << 2));
            ull bd[4] = {pk2dup(b.x), pk2dup(b.y), pk2dup(b.z), pk2dup(b.w)};
#pragma unroll
            for (int mp = 0; mp < 4; mp++)
#pragma unroll
                for (int n = 0; n < 4; n++)
                    fma2(acc2[mp][n], am[mp], bd[n]);
        }
        __syncthreads();
    }
    float4 bv = *(const float4*)(bih + g0 + (tx << 2));
#pragma unroll
    for (int mp = 0; mp < 4; mp++) {
        float2 c0 = upk2(acc2[mp][0]);
        float2 c1 = upk2(acc2[mp][1]);
        float2 c2 = upk2(acc2[mp][2]);
        float2 c3 = upk2(acc2[mp][3]);
        size_t r0 = (size_t)(t0 + (ty << 3) + 2 * mp) * G3 + g0 + (tx << 2);
        *(float4*)(g_gi + r0)      = make_float4(c0.x + bv.x, c1.x + bv.y, c2.x + bv.z, c3.x + bv.w);
        *(float4*)(g_gi + r0 + G3) = make_float4(c0.y + bv.x, c1.y + bv.y, c2.y + bv.z, c3.y + bv.w);
    }
}

// ---------------------------------------------------------------------------
// Scan role (cluster 0, CTAs 0..15) — bar-free mbarrier/st.async recurrence.
// gi consumption gated on g2done[chunk] at the 32 chunk boundaries.
// ---------------------------------------------------------------------------
__device__ void scan_role(const float* __restrict__ Whh, const float* __restrict__ bhh,
                          char* dynsm)
{
    ull*   mbar = (ull*)dynsm;                       // 16 B
    float* hT   = (float*)(dynsm + 16);              // 2*512 floats
    char*  Wbase = dynsm + 16 + 4096;                // 32 KB group-5 weights

    const int tid  = threadIdx.x;
    const int lane = tid & 31;
    const int w    = tid >> 5;
    const int cta  = blockIdx.x;          // == cluster rank for cluster 0
    const int c4   = lane & 15;
    const int rh   = lane >> 4;

    const int ui    = ((lane & 1) << 1) | rh;
    const int q     = (lane >> 1) & 7;
    const int ul    = (w << 2) + ui;
    const int u_gbl = (cta << 5) + ul;

    // Wsh element addr: [( (w*2+rh)*8 + j )*16 + c4] float4
    float4* Wsh = (float4*)Wbase;
    const int wrow = (w * 2 + rh) * 8;

    // --- one-time weight staging ---
    ull wreg[5][16];
#pragma unroll
    for (int g = 0; g < 5; g++) {
        int grow = ((g >> 1) << 9) + (cta << 5) + (w << 2) + ((g & 1) << 1) + rh;
        const ull* src = (const ull*)(Whh + (size_t)grow * HD + (c4 << 5));
#pragma unroll
        for (int k = 0; k < 16; k++) wreg[g][k] = src[k];
    }
    {   // group 5 (gate n, ui = 2+rh) -> smem
        int grow = (2 << 9) + (cta << 5) + (w << 2) + 2 + rh;
        const float4* src = (const float4*)(Whh + (size_t)grow * HD + (c4 << 5));
#pragma unroll
        for (int j = 0; j < 8; j++) Wsh[(wrow + j) * 16 + c4] = src[j];
    }
    const float br = bhh[u_gbl];
    const float bz = bhh[HD + u_gbl];
    const float bn = bhh[2 * HD + u_gbl];

    for (int i = tid; i < HD; i += 256) hT[i] = 0.0f;
    if (tid == 0) { mbar_init(smem_u32(&mbar[0]), 1); mbar_init(smem_u32(&mbar[1]), 1); }
    __syncthreads();
    cluster_sync_all();

    // precompute remote addresses (2 ranks x 2 buffers)
    const int hoffb = ((ul >> 2) << 6) + (cta << 2) + (ul & 3);
    unsigned rdata[2][2], rbar[2][2];
#pragma unroll
    for (int b = 0; b < 2; b++) {
        unsigned ld = smem_u32(&hT[(b << 9) + hoffb]);
        unsigned lm = smem_u32(&mbar[b]);
#pragma unroll
        for (int r = 0; r < 2; r++) {
            rdata[b][r] = mapa_u32(ld, (q << 1) + r);
            rbar[b][r]  = mapa_u32(lm, (q << 1) + r);
        }
    }

    // wait for gi chunk 0, then preload t=0
    while (ld_acq(&g2done[0]) < 24u) { }
    float gir, giz, gin;
    {
        const float* gp = g_gi + u_gbl;
        gir = __ldg(gp); giz = __ldg(gp + HD); gin = __ldg(gp + 2 * HD);
    }

    int ph0 = 0, ph1 = 0;
    const bool b0 = (lane & 1);
    for (int t = 0; t < T_STEPS; t++) {
        const int cb = t & 1;
        const int nb = cb ^ 1;

        if (tid == 0) mbar_expect(smem_u32(&mbar[nb]), 2048u);

        // gate gi prefetch on chunk readiness at boundaries
        if ((t + 1) < T_STEPS && (((t + 1) & 127) == 0)) {
            const unsigned* fl = &g2done[(t + 1) >> 7];
            while (ld_acq(fl) < 24u) { }
        }
        float girn, gizn, ginn;
        {
            int tn = (t + 1 < T_STEPS) ? t + 1 : t;
            const float* gp = g_gi + (size_t)tn * G3 + u_gbl;
            girn = __ldg(gp); gizn = __ldg(gp + HD); ginn = __ldg(gp + 2 * HD);
        }

        // load h chunk (32 floats)
        ull h2[16];
        {
            const longlong2* hp = (const longlong2*)(hT + (cb << 9));
#pragma unroll
            for (int j = 0; j < 8; j++) {
                longlong2 qv = hp[(j << 4) + c4];
                h2[2 * j]     = (ull)qv.x;
                h2[2 * j + 1] = (ull)qv.y;
            }
        }
        float hold = hT[(cb << 9) + hoffb];

        // matvec: 6 groups
        float accs[6];
#pragma unroll
        for (int g = 0; g < 5; g++) {
            ull a = 0ull;
#pragma unroll
            for (int k = 0; k < 16; k++) fma2(a, wreg[g][k], h2[k]);
            float2 u2 = upk2(a);
            accs[g] = u2.x + u2.y;
        }
        {
            ull a = 0ull;
            const longlong2* wp = (const longlong2*)(Wsh + wrow * 16 + c4);
#pragma unroll
            for (int j = 0; j < 8; j++) {
                longlong2 qv = wp[j << 4];
                fma2(a, (ull)qv.x, h2[2 * j]);
                fma2(a, (ull)qv.y, h2[2 * j + 1]);
            }
            float2 u2 = upk2(a);
            accs[5] = u2.x + u2.y;
        }

        // xor butterfly levels 8,4,2 on all 6 groups
#pragma unroll
        for (int d = 8; d > 1; d >>= 1)
#pragma unroll
            for (int g = 0; g < 6; g++)
                accs[g] += __shfl_xor_sync(0xffffffffu, accs[g], d);

        // level 1 with partner-swap: lane provides the partial its partner needs
        float v0 = b0 ? accs[0] : accs[1];
        float v1 = b0 ? accs[2] : accs[3];
        float v2 = b0 ? accs[4] : accs[5];
        float pr = (b0 ? accs[1] : accs[0]) + __shfl_xor_sync(0xffffffffu, v0, 1);
        float pz = (b0 ? accs[3] : accs[2]) + __shfl_xor_sync(0xffffffffu, v1, 1);
        float pn = (b0 ? accs[5] : accs[4]) + __shfl_xor_sync(0xffffffffu, v2, 1);

        float rg = fmaf(0.5f, tanh_fast(0.5f * (gir + pr + br)), 0.5f);
        float zg = fmaf(0.5f, tanh_fast(0.5f * (giz + pz + bz)), 0.5f);
        float ng = tanh_fast(fmaf(rg, pn + bn, gin));
        float hnew = fmaf(zg, hold - ng, ng);

        if (q == 0) g_hs[(size_t)t * HD + u_gbl] = hnew;

        unsigned hv = __float_as_uint(hnew);
        st_async_pre(rdata[nb][0], rbar[nb][0], hv);
        st_async_pre(rdata[nb][1], rbar[nb][1], hv);

        gir = girn; giz = gizn; gin = ginn;

        unsigned par = nb ? (unsigned)ph1 : (unsigned)ph0;
        mbar_wait(smem_u32(&mbar[nb]), par);
        if (nb) ph1 ^= 1; else ph0 ^= 1;
    }
    cluster_sync_all();
}

// ---------------------------------------------------------------------------
// Mega kernel: 128 CTAs (8 clusters of 16). Cluster 0 = scan; 112 workers
// stream GEMM1 then GEMM2 tiles with flag-based release/acquire sync.
// ---------------------------------------------------------------------------
#define MEGA_GRID 128
#define MEGA_DYN  36880

__global__ void __launch_bounds__(256, 1)
mega_kernel(const float* __restrict__ H, const float* __restrict__ X,
            const float* __restrict__ Wih, const float* __restrict__ bih,
            const float* __restrict__ Whh, const float* __restrict__ bhh)
{
    extern __shared__ char dynsm[];
    if (blockIdx.x < 16) {
        scan_role(Whh, bhh, dynsm);
        return;
    }
    const int wk = blockIdx.x - 16;   // 0..111

    // GEMM1: 256 tiles (tc = j>>3 ascending -> chunk 0 finishes first)
    for (int j = wk; j < 256; j += 112) {
        gemm1_tile(H, X, j >> 3, j & 7, dynsm);
        __threadfence();
        __syncthreads();
        if (threadIdx.x == 0) atomicAdd(&g1done[j >> 3], 1u);
    }
    // GEMM2: 768 tiles (tc = j/24 ascending)
    for (int j = wk; j < 768; j += 112) {
        int tc = j / 24, gc = j % 24;
        if (threadIdx.x == 0) {
            while (ld_acq(&g1done[tc]) < 8u) { }
        }
        __syncthreads();
        gemm2_tile(Wih, bih, tc, gc, dynsm);
        __threadfence();
        __syncthreads();
        if (threadIdx.x == 0) atomicAdd(&g2done[tc], 1u);
    }
}

// ---------------------------------------------------------------------------
// Attention pooling
// ---------------------------------------------------------------------------
__global__ void __launch_bounds__(128)
att_logits_kernel(const float* __restrict__ watt)
{
    int w = blockIdx.x * 4 + (threadIdx.x >> 5);
    int lane = threadIdx.x & 31;
    for (int i = 0; i < 8; i++) {
        int t = w * 8 + i;
        const float* hp = g_hs + (size_t)t * HD;
        float acc = 0.f;
#pragma unroll
        for (int k = 0; k < 16; k++)
            acc += hp[lane + (k << 5)] * watt[lane + (k << 5)];
        acc += __shfl_xor_sync(0xffffffffu, acc, 16);
        acc += __shfl_xor_sync(0xffffffffu, acc, 8);
        acc += __shfl_xor_sync(0xffffffffu, acc, 4);
        acc += __shfl_xor_sync(0xffffffffu, acc, 2);
        acc += __shfl_xor_sync(0xffffffffu, acc, 1);
        if (lane == 0) g_logits[t] = acc;
    }
}

__global__ void __launch_bounds__(1024)
att_softmax_kernel()
{
    __shared__ float red[1024];
    int tid = threadIdx.x;
    float l[4];
    float mx = -1e30f;
#pragma unroll
    for (int i = 0; i < 4; i++) {
        l[i] = g_logits[tid + (i << 10)];
        mx = fmaxf(mx, l[i]);
    }
    red[tid] = mx;
    __syncthreads();
    for (int s = 512; s > 0; s >>= 1) {
        if (tid < s) red[tid] = fmaxf(red[tid], red[tid + s]);
        __syncthreads();
    }
    mx = red[0];
    __syncthreads();
    float e[4];
    float se = 0.f;
#pragma unroll
    for (int i = 0; i < 4; i++) {
        e[i] = __expf(l[i] - mx);
        se += e[i];
    }
    red[tid] = se;
    __syncthreads();
    for (int s = 512; s > 0; s >>= 1) {
        if (tid < s) red[tid] += red[tid + s];
        __syncthreads();
    }
    float inv = 1.0f / red[0];
#pragma unroll
    for (int i = 0; i < 4; i++)
        g_alpha[tid + (i << 10)] = e[i] * inv;
}

__global__ void __launch_bounds__(512)
att_out_kernel()
{
    int b = blockIdx.x;
    int d = threadIdx.x;
    float acc = 0.f;
    for (int i = 0; i < 128; i++) {
        int t = b * 128 + i;
        acc += g_alpha[t] * g_hs[(size_t)t * HD + d];
    }
    g_part[b * HD + d] = acc;
}

__global__ void __launch_bounds__(512)
att_final_kernel(float* __restrict__ out)
{
    int d = threadIdx.x;
    float acc = 0.f;
#pragma unroll
    for (int b = 0; b < 32; b++)
        acc += g_part[b * HD + d];
    out[d] = acc;
}

// ---------------------------------------------------------------------------
// Launch
// ---------------------------------------------------------------------------
extern "C" void kernel_launch(void* const* d_in, const int* in_sizes, int n_in,
                              void* d_out, int out_size)
{
    const float* H    = (const float*)d_in[0];
    // d_in[1] = TE (unused by reference)
    const float* X    = (const float*)d_in[2];
    const float* Wih  = (const float*)d_in[3];
    const float* Whh  = (const float*)d_in[4];
    const float* bih  = (const float*)d_in[5];
    const float* bhh  = (const float*)d_in[6];
    const float* watt = (const float*)d_in[7];
    float* out = (float*)d_out;

    init_flags_kernel<<<1, 64>>>();

    cudaFuncSetAttribute(mega_kernel,
                         cudaFuncAttributeNonPortableClusterSizeAllowed, 1);

    cudaLaunchConfig_t cfg = {};
    cfg.gridDim = dim3(MEGA_GRID, 1, 1);
    cfg.blockDim = dim3(256, 1, 1);
    cfg.dynamicSmemBytes = MEGA_DYN;
    cfg.stream = 0;
    cudaLaunchAttribute attr[1];
    attr[0].id = cudaLaunchAttributeClusterDimension;
    attr[0].val.clusterDim.x = 16;
    attr[0].val.clusterDim.y = 1;
    attr[0].val.clusterDim.z = 1;
    cfg.attrs = attr;
    cfg.numAttrs = 1;
    cudaLaunchKernelEx(&cfg, mega_kernel, H, X, Wih, bih, Whh, bhh);

    att_logits_kernel<<<128, 128>>>(watt);
    att_softmax_kernel<<<1, 1024>>>();
    att_out_kernel<<<32, 512>>>();
    att_final_kernel<<<1, 512>>>(out);
}

// round 8
// speedup vs baseline: 1.2103x; 1.2103x over previous
#include <cuda_runtime.h>
#include <cuda_bf16.h>
#include <cstdint>
#include <cstddef>

// ---------------------------------------------------------------------------
// Problem constants
// ---------------------------------------------------------------------------
#define N_CODES 4880
#define T_STEPS 4096
#define VDIM    512
#define HD      512
#define G3      1536   // 3*HD

typedef unsigned long long ull;

// ---------------------------------------------------------------------------
// Scratch (device globals — no allocation allowed)
// ---------------------------------------------------------------------------
__device__ float g_visit[(size_t)T_STEPS * VDIM];     // 8 MB
__device__ float g_gi[(size_t)T_STEPS * G3];          // 24 MB
__device__ float g_hs[(size_t)T_STEPS * HD];          // 8 MB
__device__ float g_logits[T_STEPS];
__device__ float g_alpha[T_STEPS];
__device__ float g_part[32 * HD];

// ---------------------------------------------------------------------------
// Helpers
// ---------------------------------------------------------------------------
__device__ __forceinline__ unsigned smem_u32(const void* p) {
    unsigned a;
    asm("{ .reg .u64 t; cvta.to.shared.u64 t, %1; cvt.u32.u64 %0, t; }"
        : "=r"(a) : "l"(p));
    return a;
}
__device__ __forceinline__ unsigned mapa_u32(unsigned laddr, int rk) {
    unsigned r;
    asm("mapa.shared::cluster.u32 %0, %1, %2;" : "=r"(r) : "r"(laddr), "r"(rk));
    return r;
}
__device__ __forceinline__ ull pk2(float a, float b) {
    ull r; asm("mov.b64 %0, {%1, %2};" : "=l"(r) : "f"(a), "f"(b)); return r;
}
__device__ __forceinline__ ull pk2dup(float a) { return pk2(a, a); }
__device__ __forceinline__ void fma2(ull& d, ull a, ull b) {
    asm("fma.rn.f32x2 %0, %1, %2, %0;" : "+l"(d) : "l"(a), "l"(b));
}
__device__ __forceinline__ float2 upk2(ull v) {
    float2 r; asm("mov.b64 {%0, %1}, %2;" : "=f"(r.x), "=f"(r.y) : "l"(v));
    return r;
}
__device__ __forceinline__ float tanh_fast(float x) {
    float r; asm("tanh.approx.f32 %0, %1;" : "=f"(r) : "f"(x)); return r;
}
__device__ __forceinline__ void cluster_sync_all() {
    asm volatile("barrier.cluster.arrive.aligned;" ::: "memory");
    asm volatile("barrier.cluster.wait.aligned;" ::: "memory");
}
__device__ __forceinline__ void mbar_init(unsigned a, unsigned cnt) {
    asm volatile("mbarrier.init.shared.b64 [%0], %1;" :: "r"(a), "r"(cnt) : "memory");
}
__device__ __forceinline__ void mbar_expect(unsigned a, unsigned bytes) {
    asm volatile("mbarrier.arrive.expect_tx.shared.b64 _, [%0], %1;"
                 :: "r"(a), "r"(bytes) : "memory");
}
__device__ __forceinline__ void mbar_wait(unsigned a, unsigned parity) {
    asm volatile(
        "{\n\t.reg .pred P;\n\t"
        "LW_%=:\n\t"
        "mbarrier.try_wait.parity.acquire.cluster.shared::cta.b64 P, [%0], %1, 0x989680;\n\t"
        "@P bra.uni LD_%=;\n\t"
        "bra.uni LW_%=;\n\t"
        "LD_%=:\n\t}"
        :: "r"(a), "r"(parity) : "memory");
}
__device__ __forceinline__ void st_async_pre(unsigned ra, unsigned rb, unsigned val) {
    asm volatile(
        "st.async.shared::cluster.mbarrier::complete_tx::bytes.b32 [%0], %1, [%2];"
        :: "r"(ra), "r"(val), "r"(rb) : "memory");
}

// ---------------------------------------------------------------------------
// GEMM1: visit[t][d] = sum_k H[k][t] * X[k][d]
//   128x128 tile, 256 threads, 8x8 per thread (f32x2-packed along m).
//   Grid 32x4 = 128 CTAs = one wave.
// ---------------------------------------------------------------------------
__global__ void __launch_bounds__(256)
gemm1_kernel(const float* __restrict__ H, const float* __restrict__ X)
{
    __shared__ float As[16 * 128];   // [kk][tt]
    __shared__ float Bs[16 * 128];   // [kk][dd]
    const int tid = threadIdx.x;
    const int t0 = blockIdx.x * 128;
    const int d0 = blockIdx.y * 128;
    const int tx = tid & 15;         // -> d (8 cols)
    const int ty = tid >> 4;         // -> t (8 rows)

    ull acc2[4][8];
#pragma unroll
    for (int mp = 0; mp < 4; mp++)
#pragma unroll
        for (int n = 0; n < 8; n++) acc2[mp][n] = 0ull;

    for (int k0 = 0; k0 < N_CODES; k0 += 16) {
        // A tile: 16x128 = 512 float4, contiguous along t
#pragma unroll
        for (int j = 0; j < 2; j++) {
            int idx = tid + (j << 8);
            int kk  = idx >> 5;
            int tt4 = (idx & 31) << 2;
            float4 v = *(const float4*)(H + (size_t)(k0 + kk) * T_STEPS + t0 + tt4);
            *(float4*)(As + (kk << 7) + tt4) = v;
        }
        // B tile: 16x128 = 512 float4, contiguous along d
#pragma unroll
        for (int j = 0; j < 2; j++) {
            int idx = tid + (j << 8);
            int kk  = idx >> 5;
            int dd4 = (idx & 31) << 2;
            float4 v = *(const float4*)(X + (size_t)(k0 + kk) * VDIM + d0 + dd4);
            *(float4*)(Bs + (kk << 7) + dd4) = v;
        }
        __syncthreads();
#pragma unroll
        for (int kk = 0; kk < 16; kk++) {
            const longlong2* ap = (const longlong2*)(As + (kk << 7) + (ty << 3));
            longlong2 a01 = ap[0];
            longlong2 a23 = ap[1];
            ull am[4] = {(ull)a01.x, (ull)a01.y, (ull)a23.x, (ull)a23.y};
            float4 b0 = *(const float4*)(Bs + (kk << 7) + (tx << 3));
            float4 b1 = *(const float4*)(Bs + (kk << 7) + (tx << 3) + 4);
            ull bd[8] = {pk2dup(b0.x), pk2dup(b0.y), pk2dup(b0.z), pk2dup(b0.w),
                         pk2dup(b1.x), pk2dup(b1.y), pk2dup(b1.z), pk2dup(b1.w)};
#pragma unroll
            for (int mp = 0; mp < 4; mp++)
#pragma unroll
                for (int n = 0; n < 8; n++)
                    fma2(acc2[mp][n], am[mp], bd[n]);
        }
        __syncthreads();
    }
#pragma unroll
    for (int mp = 0; mp < 4; mp++) {
        float2 c[8];
#pragma unroll
        for (int n = 0; n < 8; n++) c[n] = upk2(acc2[mp][n]);
        size_t r0 = (size_t)(t0 + (ty << 3) + 2 * mp) * VDIM + d0 + (tx << 3);
        *(float4*)(g_visit + r0)            = make_float4(c[0].x, c[1].x, c[2].x, c[3].x);
        *(float4*)(g_visit + r0 + 4)        = make_float4(c[4].x, c[5].x, c[6].x, c[7].x);
        *(float4*)(g_visit + r0 + VDIM)     = make_float4(c[0].y, c[1].y, c[2].y, c[3].y);
        *(float4*)(g_visit + r0 + VDIM + 4) = make_float4(c[4].y, c[5].y, c[6].y, c[7].y);
    }
}

// ---------------------------------------------------------------------------
// GEMM2: gi[t][g] = b_ih[g] + sum_d visit[t][d] * W_ih[g][d]
//   128x128 tile, 256 threads, 8x8 per thread. Grid 32x12.
// ---------------------------------------------------------------------------
__global__ void __launch_bounds__(256)
gemm2_kernel(const float* __restrict__ Wih, const float* __restrict__ bih)
{
    __shared__ float As[16 * 128];   // [kk][tt]
    __shared__ float Bs[16 * 128];   // [kk][gg]
    const int tid = threadIdx.x;
    const int t0 = blockIdx.x * 128;
    const int g0 = blockIdx.y * 128;
    const int tx = tid & 15;
    const int ty = tid >> 4;

    ull acc2[4][8];
#pragma unroll
    for (int mp = 0; mp < 4; mp++)
#pragma unroll
        for (int n = 0; n < 8; n++) acc2[mp][n] = 0ull;

    for (int k0 = 0; k0 < VDIM; k0 += 16) {
        // A: visit rows (k-contiguous) -> transpose into As[kk][tt]
#pragma unroll
        for (int j = 0; j < 2; j++) {
            int idx = tid + (j << 8);        // 0..511
            int tt  = idx >> 2;              // 0..127
            int kk  = (idx & 3) << 2;        // 0,4,8,12
            float4 v = *(const float4*)(g_visit + (size_t)(t0 + tt) * VDIM + k0 + kk);
            As[(kk + 0) * 128 + tt] = v.x;
            As[(kk + 1) * 128 + tt] = v.y;
            As[(kk + 2) * 128 + tt] = v.z;
            As[(kk + 3) * 128 + tt] = v.w;
        }
        // B: W_ih rows (k-contiguous) -> transpose into Bs[kk][gg]
#pragma unroll
        for (int j = 0; j < 2; j++) {
            int idx = tid + (j << 8);
            int gg  = idx >> 2;              // 0..127
            int kk  = (idx & 3) << 2;
            float4 v = *(const float4*)(Wih + (size_t)(g0 + gg) * VDIM + k0 + kk);
            Bs[(kk + 0) * 128 + gg] = v.x;
            Bs[(kk + 1) * 128 + gg] = v.y;
            Bs[(kk + 2) * 128 + gg] = v.z;
            Bs[(kk + 3) * 128 + gg] = v.w;
        }
        __syncthreads();
#pragma unroll
        for (int kk = 0; kk < 16; kk++) {
            const longlong2* ap = (const longlong2*)(As + (kk << 7) + (ty << 3));
            longlong2 a01 = ap[0];
            longlong2 a23 = ap[1];
            ull am[4] = {(ull)a01.x, (ull)a01.y, (ull)a23.x, (ull)a23.y};
            float4 b0 = *(const float4*)(Bs + (kk << 7) + (tx << 3));
            float4 b1 = *(const float4*)(Bs + (kk << 7) + (tx << 3) + 4);
            ull bd[8] = {pk2dup(b0.x), pk2dup(b0.y), pk2dup(b0.z), pk2dup(b0.w),
                         pk2dup(b1.x), pk2dup(b1.y), pk2dup(b1.z), pk2dup(b1.w)};
#pragma unroll
            for (int mp = 0; mp < 4; mp++)
#pragma unroll
                for (int n = 0; n < 8; n++)
                    fma2(acc2[mp][n], am[mp], bd[n]);
        }
        __syncthreads();
    }
    float4 bv0 = *(const float4*)(bih + g0 + (tx << 3));
    float4 bv1 = *(const float4*)(bih + g0 + (tx << 3) + 4);
#pragma unroll
    for (int mp = 0; mp < 4; mp++) {
        float2 c[8];
#pragma unroll
        for (int n = 0; n < 8; n++) c[n] = upk2(acc2[mp][n]);
        size_t r0 = (size_t)(t0 + (ty << 3) + 2 * mp) * G3 + g0 + (tx << 3);
        *(float4*)(g_gi + r0)          = make_float4(c[0].x + bv0.x, c[1].x + bv0.y,
                                                     c[2].x + bv0.z, c[3].x + bv0.w);
        *(float4*)(g_gi + r0 + 4)      = make_float4(c[4].x + bv1.x, c[5].x + bv1.y,
                                                     c[6].x + bv1.z, c[7].x + bv1.w);
        *(float4*)(g_gi + r0 + G3)     = make_float4(c[0].y + bv0.x, c[1].y + bv0.y,
                                                     c[2].y + bv0.z, c[3].y + bv0.w);
        *(float4*)(g_gi + r0 + G3 + 4) = make_float4(c[4].y + bv1.x, c[5].y + bv1.y,
                                                     c[6].y + bv1.z, c[7].y + bv1.w);
    }
}

// ---------------------------------------------------------------------------
// GRU scan: 16-CTA cluster, 256 threads (8 warps), BAR-FREE loop
// (mbarrier + st.async recurrence). Partner-swap final shuffle level.
// ---------------------------------------------------------------------------
#define SCAN_THREADS 256

__global__ void __launch_bounds__(SCAN_THREADS, 1)
scan_kernel(const float* __restrict__ Whh, const float* __restrict__ bhh)
{
    __shared__ float4 Wsh4[8][2][8][16];  // group-5 weights [w][rh][j][c4] : 32 KB
    __shared__ float  hT[2 * HD];         // transposed h, 2 buffers
    __shared__ ull    mbar[2];

    const int tid  = threadIdx.x;
    const int lane = tid & 31;
    const int w    = tid >> 5;
    const int cta  = blockIdx.x;          // cluster rank
    const int c4   = lane & 15;           // h-chunk (source CTA) index
    const int rh   = lane >> 4;

    const int ui    = ((lane & 1) << 1) | rh;
    const int q     = (lane >> 1) & 7;
    const int ul    = (w << 2) + ui;
    const int u_gbl = (cta << 5) + ul;

    // --- one-time weight staging ---
    ull wreg[5][16];
#pragma unroll
    for (int g = 0; g < 5; g++) {
        int grow = ((g >> 1) << 9) + (cta << 5) + (w << 2) + ((g & 1) << 1) + rh;
        const ull* src = (const ull*)(Whh + (size_t)grow * HD + (c4 << 5));
#pragma unroll
        for (int k = 0; k < 16; k++) wreg[g][k] = src[k];
    }
    {   // group 5 (gate n, ui = 2+rh) -> smem
        int grow = (2 << 9) + (cta << 5) + (w << 2) + 2 + rh;
        const float4* src = (const float4*)(Whh + (size_t)grow * HD + (c4 << 5));
#pragma unroll
        for (int j = 0; j < 8; j++) Wsh4[w][rh][j][c4] = src[j];
    }
    const float br = bhh[u_gbl];
    const float bz = bhh[HD + u_gbl];
    const float bn = bhh[2 * HD + u_gbl];

    for (int i = tid; i < HD; i += SCAN_THREADS) hT[i] = 0.0f;
    if (tid == 0) { mbar_init(smem_u32(&mbar[0]), 1); mbar_init(smem_u32(&mbar[1]), 1); }
    __syncthreads();
    cluster_sync_all();

    // precompute remote addresses (2 ranks x 2 buffers)
    const int hoffb = ((ul >> 2) << 6) + (cta << 2) + (ul & 3);
    unsigned rdata[2][2], rbar[2][2];
#pragma unroll
    for (int b = 0; b < 2; b++) {
        unsigned ld = smem_u32(&hT[(b << 9) + hoffb]);
        unsigned lm = smem_u32(&mbar[b]);
#pragma unroll
        for (int r = 0; r < 2; r++) {
            rdata[b][r] = mapa_u32(ld, (q << 1) + r);
            rbar[b][r]  = mapa_u32(lm, (q << 1) + r);
        }
    }

    // gi preload for t=0
    float gir, giz, gin;
    {
        const float* gp = g_gi + u_gbl;
        gir = __ldg(gp); giz = __ldg(gp + HD); gin = __ldg(gp + 2 * HD);
    }

    int ph0 = 0, ph1 = 0;
    const bool b0 = (lane & 1);
    for (int t = 0; t < T_STEPS; t++) {
        const int cb = t & 1;
        const int nb = cb ^ 1;

        if (tid == 0) mbar_expect(smem_u32(&mbar[nb]), 2048u);

        // prefetch gi for t+1
        float girn, gizn, ginn;
        {
            int tn = (t + 1 < T_STEPS) ? t + 1 : t;
            const float* gp = g_gi + (size_t)tn * G3 + u_gbl;
            girn = __ldg(gp); gizn = __ldg(gp + HD); ginn = __ldg(gp + 2 * HD);
        }

        // load h chunk (32 floats) — transposed layout, conflict-free
        ull h2[16];
        {
            const longlong2* hp = (const longlong2*)(hT + (cb << 9));
#pragma unroll
            for (int j = 0; j < 8; j++) {
                longlong2 qv = hp[(j << 4) + c4];
                h2[2 * j]     = (ull)qv.x;
                h2[2 * j + 1] = (ull)qv.y;
            }
        }
        float hold = hT[(cb << 9) + hoffb];

        // matvec: 6 groups
        float accs[6];
#pragma unroll
        for (int g = 0; g < 5; g++) {
            ull a = 0ull;
#pragma unroll
            for (int k = 0; k < 16; k++) fma2(a, wreg[g][k], h2[k]);
            float2 u2 = upk2(a);
            accs[g] = u2.x + u2.y;
        }
        {
            ull a = 0ull;
            const longlong2* wp = (const longlong2*)&Wsh4[w][rh][0][c4];
#pragma unroll
            for (int j = 0; j < 8; j++) {
                longlong2 qv = wp[j << 4];
                fma2(a, (ull)qv.x, h2[2 * j]);
                fma2(a, (ull)qv.y, h2[2 * j + 1]);
            }
            float2 u2 = upk2(a);
            accs[5] = u2.x + u2.y;
        }

        // xor butterfly levels 8,4,2
#pragma unroll
        for (int d = 8; d > 1; d >>= 1)
#pragma unroll
            for (int g = 0; g < 6; g++)
                accs[g] += __shfl_xor_sync(0xffffffffu, accs[g], d);

        // level 1 with partner-swap: send the partial the partner needs
        float v0 = b0 ? accs[0] : accs[1];
        float v1 = b0 ? accs[2] : accs[3];
        float v2 = b0 ? accs[4] : accs[5];
        float pr = (b0 ? accs[1] : accs[0]) + __shfl_xor_sync(0xffffffffu, v0, 1);
        float pz = (b0 ? accs[3] : accs[2]) + __shfl_xor_sync(0xffffffffu, v1, 1);
        float pn = (b0 ? accs[5] : accs[4]) + __shfl_xor_sync(0xffffffffu, v2, 1);

        float rg = fmaf(0.5f, tanh_fast(0.5f * (gir + pr + br)), 0.5f);
        float zg = fmaf(0.5f, tanh_fast(0.5f * (giz + pz + bz)), 0.5f);
        float ng = tanh_fast(fmaf(rg, pn + bn, gin));
        float hnew = fmaf(zg, hold - ng, ng);

        if (q == 0) g_hs[(size_t)t * HD + u_gbl] = hnew;

        unsigned hv = __float_as_uint(hnew);
        st_async_pre(rdata[nb][0], rbar[nb][0], hv);
        st_async_pre(rdata[nb][1], rbar[nb][1], hv);

        gir = girn; giz = gizn; gin = ginn;

        unsigned par = nb ? (unsigned)ph1 : (unsigned)ph0;
        mbar_wait(smem_u32(&mbar[nb]), par);
        if (nb) ph1 ^= 1; else ph0 ^= 1;
    }
    cluster_sync_all();
}

// ---------------------------------------------------------------------------
// Attention pooling
// ---------------------------------------------------------------------------
__global__ void __launch_bounds__(128)
att_logits_kernel(const float* __restrict__ watt)
{
    int w = blockIdx.x * 4 + (threadIdx.x >> 5);
    int lane = threadIdx.x & 31;
    for (int i = 0; i < 8; i++) {
        int t = w * 8 + i;
        const float* hp = g_hs + (size_t)t * HD;
        float acc = 0.f;
#pragma unroll
        for (int k = 0; k < 16; k++)
            acc += hp[lane + (k << 5)] * watt[lane + (k << 5)];
        acc += __shfl_xor_sync(0xffffffffu, acc, 16);
        acc += __shfl_xor_sync(0xffffffffu, acc, 8);
        acc += __shfl_xor_sync(0xffffffffu, acc, 4);
        acc += __shfl_xor_sync(0xffffffffu, acc, 2);
        acc += __shfl_xor_sync(0xffffffffu, acc, 1);
        if (lane == 0) g_logits[t] = acc;
    }
}

__global__ void __launch_bounds__(1024)
att_softmax_kernel()
{
    __shared__ float red[1024];
    int tid = threadIdx.x;
    float l[4];
    float mx = -1e30f;
#pragma unroll
    for (int i = 0; i < 4; i++) {
        l[i] = g_logits[tid + (i << 10)];
        mx = fmaxf(mx, l[i]);
    }
    red[tid] = mx;
    __syncthreads();
    for (int s = 512; s > 0; s >>= 1) {
        if (tid < s) red[tid] = fmaxf(red[tid], red[tid + s]);
        __syncthreads();
    }
    mx = red[0];
    __syncthreads();
    float e[4];
    float se = 0.f;
#pragma unroll
    for (int i = 0; i < 4; i++) {
        e[i] = __expf(l[i] - mx);
        se += e[i];
    }
    red[tid] = se;
    __syncthreads();
    for (int s = 512; s > 0; s >>= 1) {
        if (tid < s) red[tid] += red[tid + s];
        __syncthreads();
    }
    float inv = 1.0f / red[0];
#pragma unroll
    for (int i = 0; i < 4; i++)
        g_alpha[tid + (i << 10)] = e[i] * inv;
}

__global__ void __launch_bounds__(512)
att_out_kernel()
{
    int b = blockIdx.x;
    int d = threadIdx.x;
    float acc = 0.f;
    for (int i = 0; i < 128; i++) {
        int t = b * 128 + i;
        acc += g_alpha[t] * g_hs[(size_t)t * HD + d];
    }
    g_part[b * HD + d] = acc;
}

__global__ void __launch_bounds__(512)
att_final_kernel(float* __restrict__ out)
{
    int d = threadIdx.x;
    float acc = 0.f;
#pragma unroll
    for (int b = 0; b < 32; b++)
        acc += g_part[b * HD + d];
    out[d] = acc;
}

// ---------------------------------------------------------------------------
// Launch — single stream, no flags, no streams/events (all proven constructs)
// ---------------------------------------------------------------------------
extern "C" void kernel_launch(void* const* d_in, const int* in_sizes, int n_in,
                              void* d_out, int out_size)
{
    const float* H    = (const float*)d_in[0];
    // d_in[1] = TE (unused by reference)
    const float* X    = (const float*)d_in[2];
    const float* Wih  = (const float*)d_in[3];
    const float* Whh  = (const float*)d_in[4];
    const float* bih  = (const float*)d_in[5];
    const float* bhh  = (const float*)d_in[6];
    const float* watt = (const float*)d_in[7];
    float* out = (float*)d_out;

    gemm1_kernel<<<dim3(32, 4), 256>>>(H, X);
    gemm2_kernel<<<dim3(32, 12), 256>>>(Wih, bih);

    cudaFuncSetAttribute(scan_kernel,
                         cudaFuncAttributeNonPortableClusterSizeAllowed, 1);

    cudaLaunchConfig_t cfg = {};
    cfg.gridDim = dim3(16, 1, 1);
    cfg.blockDim = dim3(SCAN_THREADS, 1, 1);
    cfg.dynamicSmemBytes = 0;
    cfg.stream = 0;
    cudaLaunchAttribute attr[1];
    attr[0].id = cudaLaunchAttributeClusterDimension;
    attr[0].val.clusterDim.x = 16;
    attr[0].val.clusterDim.y = 1;
    attr[0].val.clusterDim.z = 1;
    cfg.attrs = attr;
    cfg.numAttrs = 1;
    cudaLaunchKernelEx(&cfg, scan_kernel, Whh, bhh);

    att_logits_kernel<<<128, 128>>>(watt);
    att_softmax_kernel<<<1, 1024>>>();
    att_out_kernel<<<32, 512>>>();
    att_final_kernel<<<1, 512>>>(out);
}

// round 9
// speedup vs baseline: 1.2545x; 1.0365x over previous
#include <cuda_runtime.h>
#include <cuda_bf16.h>
#include <cstdint>
#include <cstddef>

// ---------------------------------------------------------------------------
// Problem constants
// ---------------------------------------------------------------------------
#define N_CODES 4880
#define T_STEPS 4096
#define VDIM    512
#define HD      512
#define G3      1536   // 3*HD

typedef unsigned long long ull;

// ---------------------------------------------------------------------------
// Scratch (device globals — no allocation allowed)
// ---------------------------------------------------------------------------
__device__ float g_visit[(size_t)T_STEPS * VDIM];     // 8 MB
__device__ float g_gi[(size_t)T_STEPS * G3];          // 24 MB
__device__ float g_hs[(size_t)T_STEPS * HD];          // 8 MB
__device__ float g_logits[T_STEPS];
__device__ float g_alpha[T_STEPS];
__device__ float g_part[32 * HD];

// ---------------------------------------------------------------------------
// Helpers
// ---------------------------------------------------------------------------
__device__ __forceinline__ unsigned smem_u32(const void* p) {
    unsigned a;
    asm("{ .reg .u64 t; cvta.to.shared.u64 t, %1; cvt.u32.u64 %0, t; }"
        : "=r"(a) : "l"(p));
    return a;
}
__device__ __forceinline__ unsigned mapa_u32(unsigned laddr, int rk) {
    unsigned r;
    asm("mapa.shared::cluster.u32 %0, %1, %2;" : "=r"(r) : "r"(laddr), "r"(rk));
    return r;
}
__device__ __forceinline__ ull pk2(float a, float b) {
    ull r; asm("mov.b64 %0, {%1, %2};" : "=l"(r) : "f"(a), "f"(b)); return r;
}
__device__ __forceinline__ ull pk2dup(float a) { return pk2(a, a); }
__device__ __forceinline__ void fma2(ull& d, ull a, ull b) {
    asm("fma.rn.f32x2 %0, %1, %2, %0;" : "+l"(d) : "l"(a), "l"(b));
}
__device__ __forceinline__ float2 upk2(ull v) {
    float2 r; asm("mov.b64 {%0, %1}, %2;" : "=f"(r.x), "=f"(r.y) : "l"(v));
    return r;
}
__device__ __forceinline__ float tanh_fast(float x) {
    float r; asm("tanh.approx.f32 %0, %1;" : "=f"(r) : "f"(x)); return r;
}
__device__ __forceinline__ void cluster_sync_all() {
    asm volatile("barrier.cluster.arrive.aligned;" ::: "memory");
    asm volatile("barrier.cluster.wait.aligned;" ::: "memory");
}
__device__ __forceinline__ void mbar_init(unsigned a, unsigned cnt) {
    asm volatile("mbarrier.init.shared.b64 [%0], %1;" :: "r"(a), "r"(cnt) : "memory");
}
__device__ __forceinline__ void mbar_expect(unsigned a, unsigned bytes) {
    asm volatile("mbarrier.arrive.expect_tx.shared.b64 _, [%0], %1;"
                 :: "r"(a), "r"(bytes) : "memory");
}
__device__ __forceinline__ void mbar_wait(unsigned a, unsigned parity) {
    asm volatile(
        "{\n\t.reg .pred P;\n\t"
        "LW_%=:\n\t"
        "mbarrier.try_wait.parity.acquire.cluster.shared::cta.b64 P, [%0], %1, 0x989680;\n\t"
        "@P bra.uni LD_%=;\n\t"
        "bra.uni LW_%=;\n\t"
        "LD_%=:\n\t}"
        :: "r"(a), "r"(parity) : "memory");
}
__device__ __forceinline__ void st_async_pre(unsigned ra, unsigned rb, unsigned val) {
    asm volatile(
        "st.async.shared::cluster.mbarrier::complete_tx::bytes.b32 [%0], %1, [%2];"
        :: "r"(ra), "r"(val), "r"(rb) : "memory");
}

// ---------------------------------------------------------------------------
// GEMM1: visit[t][d] = sum_k H[k][t] * X[k][d]
//   128x64 tile, 256 threads, 8x4 per thread (f32x2-packed along m) — R4 config
// ---------------------------------------------------------------------------
__global__ void __launch_bounds__(256)
gemm1_kernel(const float* __restrict__ H, const float* __restrict__ X)
{
    __shared__ float As[16 * 128];
    __shared__ float Bs[16 * 64];
    const int tid = threadIdx.x;
    const int t0 = blockIdx.x * 128;
    const int d0 = blockIdx.y * 64;
    const int tx = tid & 15;
    const int ty = tid >> 4;

    ull acc2[4][4];
#pragma unroll
    for (int mp = 0; mp < 4; mp++)
#pragma unroll
        for (int n = 0; n < 4; n++) acc2[mp][n] = 0ull;

    for (int k0 = 0; k0 < N_CODES; k0 += 16) {
#pragma unroll
        for (int j = 0; j < 2; j++) {
            int idx = tid + (j << 8);
            int kk  = idx >> 5;
            int tt4 = (idx & 31) << 2;
            float4 v = *(const float4*)(H + (size_t)(k0 + kk) * T_STEPS + t0 + tt4);
            *(float4*)(As + (kk << 7) + tt4) = v;
        }
        {
            int kk  = tid >> 4;
            int dd4 = (tid & 15) << 2;
            float4 v = *(const float4*)(X + (size_t)(k0 + kk) * VDIM + d0 + dd4);
            *(float4*)(Bs + (kk << 6) + dd4) = v;
        }
        __syncthreads();
#pragma unroll
        for (int kk = 0; kk < 16; kk++) {
            const longlong2* ap = (const longlong2*)(As + (kk << 7) + (ty << 3));
            longlong2 a01 = ap[0];
            longlong2 a23 = ap[1];
            ull am[4] = {(ull)a01.x, (ull)a01.y, (ull)a23.x, (ull)a23.y};
            float4 b = *(const float4*)(Bs + (kk << 6) + (tx << 2));
            ull bd[4] = {pk2dup(b.x), pk2dup(b.y), pk2dup(b.z), pk2dup(b.w)};
#pragma unroll
            for (int mp = 0; mp < 4; mp++)
#pragma unroll
                for (int n = 0; n < 4; n++)
                    fma2(acc2[mp][n], am[mp], bd[n]);
        }
        __syncthreads();
    }
#pragma unroll
    for (int mp = 0; mp < 4; mp++) {
        float2 c0 = upk2(acc2[mp][0]);
        float2 c1 = upk2(acc2[mp][1]);
        float2 c2 = upk2(acc2[mp][2]);
        float2 c3 = upk2(acc2[mp][3]);
        size_t r0 = (size_t)(t0 + (ty << 3) + 2 * mp) * VDIM + d0 + (tx << 2);
        *(float4*)(g_visit + r0)        = make_float4(c0.x, c1.x, c2.x, c3.x);
        *(float4*)(g_visit + r0 + VDIM) = make_float4(c0.y, c1.y, c2.y, c3.y);
    }
}

// ---------------------------------------------------------------------------
// GEMM2: gi[t][g] = b_ih[g] + sum_d visit[t][d] * W_ih[g][d]  — R4 config
// ---------------------------------------------------------------------------
__global__ void __launch_bounds__(256)
gemm2_kernel(const float* __restrict__ Wih, const float* __restrict__ bih)
{
    __shared__ float As[16 * 128];
    __shared__ float Bs[16 * 64];
    const int tid = threadIdx.x;
    const int t0 = blockIdx.x * 128;
    const int g0 = blockIdx.y * 64;
    const int tx = tid & 15;
    const int ty = tid >> 4;

    ull acc2[4][4];
#pragma unroll
    for (int mp = 0; mp < 4; mp++)
#pragma unroll
        for (int n = 0; n < 4; n++) acc2[mp][n] = 0ull;

    for (int k0 = 0; k0 < VDIM; k0 += 16) {
#pragma unroll
        for (int j = 0; j < 2; j++) {
            int idx = tid + (j << 8);
            int tt  = idx >> 2;
            int kk  = (idx & 3) << 2;
            float4 v = *(const float4*)(g_visit + (size_t)(t0 + tt) * VDIM + k0 + kk);
            As[(kk + 0) * 128 + tt] = v.x;
            As[(kk + 1) * 128 + tt] = v.y;
            As[(kk + 2) * 128 + tt] = v.z;
            As[(kk + 3) * 128 + tt] = v.w;
        }
        {
            int gg = tid >> 2;
            int kk = (tid & 3) << 2;
            float4 v = *(const float4*)(Wih + (size_t)(g0 + gg) * VDIM + k0 + kk);
            Bs[(kk + 0) * 64 + gg] = v.x;
            Bs[(kk + 1) * 64 + gg] = v.y;
            Bs[(kk + 2) * 64 + gg] = v.z;
            Bs[(kk + 3) * 64 + gg] = v.w;
        }
        __syncthreads();
#pragma unroll
        for (int kk = 0; kk < 16; kk++) {
            const longlong2* ap = (const longlong2*)(As + (kk << 7) + (ty << 3));
            longlong2 a01 = ap[0];
            longlong2 a23 = ap[1];
            ull am[4] = {(ull)a01.x, (ull)a01.y, (ull)a23.x, (ull)a23.y};
            float4 b = *(const float4*)(Bs + (kk << 6) + (tx << 2));
            ull bd[4] = {pk2dup(b.x), pk2dup(b.y), pk2dup(b.z), pk2dup(b.w)};
#pragma unroll
            for (int mp = 0; mp < 4; mp++)
#pragma unroll
                for (int n = 0; n < 4; n++)
                    fma2(acc2[mp][n], am[mp], bd[n]);
        }
        __syncthreads();
    }
    float4 bv = *(const float4*)(bih + g0 + (tx << 2));
#pragma unroll
    for (int mp = 0; mp < 4; mp++) {
        float2 c0 = upk2(acc2[mp][0]);
        float2 c1 = upk2(acc2[mp][1]);
        float2 c2 = upk2(acc2[mp][2]);
        float2 c3 = upk2(acc2[mp][3]);
        size_t r0 = (size_t)(t0 + (ty << 3) + 2 * mp) * G3 + g0 + (tx << 2);
        *(float4*)(g_gi + r0)      = make_float4(c0.x + bv.x, c1.x + bv.y, c2.x + bv.z, c3.x + bv.w);
        *(float4*)(g_gi + r0 + G3) = make_float4(c0.y + bv.x, c1.y + bv.y, c2.y + bv.z, c3.y + bv.w);
    }
}

// ---------------------------------------------------------------------------
// GRU scan: 16-CTA cluster, 256 threads (8 warps), BAR-FREE loop
// (mbarrier + st.async recurrence). Partner-swap final shuffle level.
// ---------------------------------------------------------------------------
#define SCAN_THREADS 256

__global__ void __launch_bounds__(SCAN_THREADS, 1)
scan_kernel(const float* __restrict__ Whh, const float* __restrict__ bhh)
{
    __shared__ float4 Wsh4[8][2][8][16];  // group-5 weights [w][rh][j][c4] : 32 KB
    __shared__ float  hT[2 * HD];         // transposed h, 2 buffers
    __shared__ ull    mbar[2];

    const int tid  = threadIdx.x;
    const int lane = tid & 31;
    const int w    = tid >> 5;
    const int cta  = blockIdx.x;          // cluster rank
    const int c4   = lane & 15;           // h-chunk (source CTA) index
    const int rh   = lane >> 4;

    const int ui    = ((lane & 1) << 1) | rh;
    const int q     = (lane >> 1) & 7;
    const int ul    = (w << 2) + ui;
    const int u_gbl = (cta << 5) + ul;

    // --- one-time weight staging ---
    ull wreg[5][16];
#pragma unroll
    for (int g = 0; g < 5; g++) {
        int grow = ((g >> 1) << 9) + (cta << 5) + (w << 2) + ((g & 1) << 1) + rh;
        const ull* src = (const ull*)(Whh + (size_t)grow * HD + (c4 << 5));
#pragma unroll
        for (int k = 0; k < 16; k++) wreg[g][k] = src[k];
    }
    {   // group 5 (gate n, ui = 2+rh) -> smem
        int grow = (2 << 9) + (cta << 5) + (w << 2) + 2 + rh;
        const float4* src = (const float4*)(Whh + (size_t)grow * HD + (c4 << 5));
#pragma unroll
        for (int j = 0; j < 8; j++) Wsh4[w][rh][j][c4] = src[j];
    }
    const float br = bhh[u_gbl];
    const float bz = bhh[HD + u_gbl];
    const float bn = bhh[2 * HD + u_gbl];

    for (int i = tid; i < HD; i += SCAN_THREADS) hT[i] = 0.0f;
    if (tid == 0) { mbar_init(smem_u32(&mbar[0]), 1); mbar_init(smem_u32(&mbar[1]), 1); }
    __syncthreads();
    cluster_sync_all();

    // precompute remote addresses (2 ranks x 2 buffers)
    const int hoffb = ((ul >> 2) << 6) + (cta << 2) + (ul & 3);
    unsigned rdata[2][2], rbar[2][2];
#pragma unroll
    for (int b = 0; b < 2; b++) {
        unsigned ld = smem_u32(&hT[(b << 9) + hoffb]);
        unsigned lm = smem_u32(&mbar[b]);
#pragma unroll
        for (int r = 0; r < 2; r++) {
            rdata[b][r] = mapa_u32(ld, (q << 1) + r);
            rbar[b][r]  = mapa_u32(lm, (q << 1) + r);
        }
    }

    // gi preload for t=0
    float gir, giz, gin;
    {
        const float* gp = g_gi + u_gbl;
        gir = __ldg(gp); giz = __ldg(gp + HD); gin = __ldg(gp + 2 * HD);
    }

    int ph0 = 0, ph1 = 0;
    const bool b0 = (lane & 1);
    for (int t = 0; t < T_STEPS; t++) {
        const int cb = t & 1;
        const int nb = cb ^ 1;

        if (tid == 0) mbar_expect(smem_u32(&mbar[nb]), 2048u);

        // prefetch gi for t+1
        float girn, gizn, ginn;
        {
            int tn = (t + 1 < T_STEPS) ? t + 1 : t;
            const float* gp = g_gi + (size_t)tn * G3 + u_gbl;
            girn = __ldg(gp); gizn = __ldg(gp + HD); ginn = __ldg(gp + 2 * HD);
        }

        // load h chunk (32 floats) — transposed layout, conflict-free
        ull h2[16];
        {
            const longlong2* hp = (const longlong2*)(hT + (cb << 9));
#pragma unroll
            for (int j = 0; j < 8; j++) {
                longlong2 qv = hp[(j << 4) + c4];
                h2[2 * j]     = (ull)qv.x;
                h2[2 * j + 1] = (ull)qv.y;
            }
        }
        float hold = hT[(cb << 9) + hoffb];

        // matvec: 6 groups
        float accs[6];
#pragma unroll
        for (int g = 0; g < 5; g++) {
            ull a = 0ull;
#pragma unroll
            for (int k = 0; k < 16; k++) fma2(a, wreg[g][k], h2[k]);
            float2 u2 = upk2(a);
            accs[g] = u2.x + u2.y;
        }
        {
            ull a = 0ull;
            const longlong2* wp = (const longlong2*)&Wsh4[w][rh][0][c4];
#pragma unroll
            for (int j = 0; j < 8; j++) {
                longlong2 qv = wp[j << 4];
                fma2(a, (ull)qv.x, h2[2 * j]);
                fma2(a, (ull)qv.y, h2[2 * j + 1]);
            }
            float2 u2 = upk2(a);
            accs[5] = u2.x + u2.y;
        }

        // xor butterfly levels 8,4,2
#pragma unroll
        for (int d = 8; d > 1; d >>= 1)
#pragma unroll
            for (int g = 0; g < 6; g++)
                accs[g] += __shfl_xor_sync(0xffffffffu, accs[g], d);

        // level 1 with partner-swap: send the partial the partner needs
        float v0 = b0 ? accs[0] : accs[1];
        float v1 = b0 ? accs[2] : accs[3];
        float v2 = b0 ? accs[4] : accs[5];
        float pr = (b0 ? accs[1] : accs[0]) + __shfl_xor_sync(0xffffffffu, v0, 1);
        float pz = (b0 ? accs[3] : accs[2]) + __shfl_xor_sync(0xffffffffu, v1, 1);
        float pn = (b0 ? accs[5] : accs[4]) + __shfl_xor_sync(0xffffffffu, v2, 1);

        float rg = fmaf(0.5f, tanh_fast(0.5f * (gir + pr + br)), 0.5f);
        float zg = fmaf(0.5f, tanh_fast(0.5f * (giz + pz + bz)), 0.5f);
        float ng = tanh_fast(fmaf(rg, pn + bn, gin));
        float hnew = fmaf(zg, hold - ng, ng);

        if (q == 0) g_hs[(size_t)t * HD + u_gbl] = hnew;

        unsigned hv = __float_as_uint(hnew);
        st_async_pre(rdata[nb][0], rbar[nb][0], hv);
        st_async_pre(rdata[nb][1], rbar[nb][1], hv);

        gir = girn; giz = gizn; gin = ginn;

        unsigned par = nb ? (unsigned)ph1 : (unsigned)ph0;
        mbar_wait(smem_u32(&mbar[nb]), par);
        if (nb) ph1 ^= 1; else ph0 ^= 1;
    }
    cluster_sync_all();
}

// ---------------------------------------------------------------------------
// Attention pooling
// ---------------------------------------------------------------------------
__global__ void __launch_bounds__(128)
att_logits_kernel(const float* __restrict__ watt)
{
    int w = blockIdx.x * 4 + (threadIdx.x >> 5);
    int lane = threadIdx.x & 31;
    for (int i = 0; i < 8; i++) {
        int t = w * 8 + i;
        const float* hp = g_hs + (size_t)t * HD;
        float acc = 0.f;
#pragma unroll
        for (int k = 0; k < 16; k++)
            acc += hp[lane + (k << 5)] * watt[lane + (k << 5)];
        acc += __shfl_xor_sync(0xffffffffu, acc, 16);
        acc += __shfl_xor_sync(0xffffffffu, acc, 8);
        acc += __shfl_xor_sync(0xffffffffu, acc, 4);
        acc += __shfl_xor_sync(0xffffffffu, acc, 2);
        acc += __shfl_xor_sync(0xffffffffu, acc, 1);
        if (lane == 0) g_logits[t] = acc;
    }
}

__global__ void __launch_bounds__(1024)
att_softmax_kernel()
{
    __shared__ float red[1024];
    int tid = threadIdx.x;
    float l[4];
    float mx = -1e30f;
#pragma unroll
    for (int i = 0; i < 4; i++) {
        l[i] = g_logits[tid + (i << 10)];
        mx = fmaxf(mx, l[i]);
    }
    red[tid] = mx;
    __syncthreads();
    for (int s = 512; s > 0; s >>= 1) {
        if (tid < s) red[tid] = fmaxf(red[tid], red[tid + s]);
        __syncthreads();
    }
    mx = red[0];
    __syncthreads();
    float e[4];
    float se = 0.f;
#pragma unroll
    for (int i = 0; i < 4; i++) {
        e[i] = __expf(l[i] - mx);
        se += e[i];
    }
    red[tid] = se;
    __syncthreads();
    for (int s = 512; s > 0; s >>= 1) {
        if (tid < s) red[tid] += red[tid + s];
        __syncthreads();
    }
    float inv = 1.0f / red[0];
#pragma unroll
    for (int i = 0; i < 4; i++)
        g_alpha[tid + (i << 10)] = e[i] * inv;
}

__global__ void __launch_bounds__(512)
att_out_kernel()
{
    int b = blockIdx.x;
    int d = threadIdx.x;
    float acc = 0.f;
    for (int i = 0; i < 128; i++) {
        int t = b * 128 + i;
        acc += g_alpha[t] * g_hs[(size_t)t * HD + d];
    }
    g_part[b * HD + d] = acc;
}

__global__ void __launch_bounds__(512)
att_final_kernel(float* __restrict__ out)
{
    int d = threadIdx.x;
    float acc = 0.f;
#pragma unroll
    for (int b = 0; b < 32; b++)
        acc += g_part[b * HD + d];
    out[d] = acc;
}

// ---------------------------------------------------------------------------
// Launch — single stream (proven R4 structure)
// ---------------------------------------------------------------------------
extern "C" void kernel_launch(void* const* d_in, const int* in_sizes, int n_in,
                              void* d_out, int out_size)
{
    const float* H    = (const float*)d_in[0];
    // d_in[1] = TE (unused by reference)
    const float* X    = (const float*)d_in[2];
    const float* Wih  = (const float*)d_in[3];
    const float* Whh  = (const float*)d_in[4];
    const float* bih  = (const float*)d_in[5];
    const float* bhh  = (const float*)d_in[6];
    const float* watt = (const float*)d_in[7];
    float* out = (float*)d_out;

    gemm1_kernel<<<dim3(32, 8), 256>>>(H, X);
    gemm2_kernel<<<dim3(32, 24), 256>>>(Wih, bih);

    cudaFuncSetAttribute(scan_kernel,
                         cudaFuncAttributeNonPortableClusterSizeAllowed, 1);

    cudaLaunchConfig_t cfg = {};
    cfg.gridDim = dim3(16, 1, 1);
    cfg.blockDim = dim3(SCAN_THREADS, 1, 1);
    cfg.dynamicSmemBytes = 0;
    cfg.stream = 0;
    cudaLaunchAttribute attr[1];
    attr[0].id = cudaLaunchAttributeClusterDimension;
    attr[0].val.clusterDim.x = 16;
    attr[0].val.clusterDim.y = 1;
    attr[0].val.clusterDim.z = 1;
    cfg.attrs = attr;
    cfg.numAttrs = 1;
    cudaLaunchKernelEx(&cfg, scan_kernel, Whh, bhh);

    att_logits_kernel<<<128, 128>>>(watt);
    att_softmax_kernel<<<1, 1024>>>();
    att_out_kernel<<<32, 512>>>();
    att_final_kernel<<<1, 512>>>(out);
}

// round 10
// speedup vs baseline: 1.2615x; 1.0056x over previous
#include <cuda_runtime.h>
#include <cuda_bf16.h>
#include <cstdint>
#include <cstddef>

// ---------------------------------------------------------------------------
// Problem constants
// ---------------------------------------------------------------------------
#define N_CODES 4880
#define T_STEPS 4096
#define VDIM    512
#define HD      512
#define G3      1536   // 3*HD

typedef unsigned long long ull;

// ---------------------------------------------------------------------------
// Scratch (device globals — no allocation allowed)
// ---------------------------------------------------------------------------
__device__ float g_visit[(size_t)T_STEPS * VDIM];     // 8 MB
__device__ float g_gi[(size_t)T_STEPS * G3];          // 24 MB
__device__ float g_hs[(size_t)T_STEPS * HD];          // 8 MB
__device__ float g_logits[T_STEPS];
__device__ float g_alpha[T_STEPS];
__device__ float g_part[32 * HD];

// ---------------------------------------------------------------------------
// Helpers
// ---------------------------------------------------------------------------
__device__ __forceinline__ unsigned smem_u32(const void* p) {
    unsigned a;
    asm("{ .reg .u64 t; cvta.to.shared.u64 t, %1; cvt.u32.u64 %0, t; }"
        : "=r"(a) : "l"(p));
    return a;
}
__device__ __forceinline__ unsigned mapa_u32(unsigned laddr, int rk) {
    unsigned r;
    asm("mapa.shared::cluster.u32 %0, %1, %2;" : "=r"(r) : "r"(laddr), "r"(rk));
    return r;
}
__device__ __forceinline__ ull pk2(float a, float b) {
    ull r; asm("mov.b64 %0, {%1, %2};" : "=l"(r) : "f"(a), "f"(b)); return r;
}
__device__ __forceinline__ ull pk2dup(float a) { return pk2(a, a); }
__device__ __forceinline__ void fma2(ull& d, ull a, ull b) {
    asm("fma.rn.f32x2 %0, %1, %2, %0;" : "+l"(d) : "l"(a), "l"(b));
}
__device__ __forceinline__ float2 upk2(ull v) {
    float2 r; asm("mov.b64 {%0, %1}, %2;" : "=f"(r.x), "=f"(r.y) : "l"(v));
    return r;
}
__device__ __forceinline__ float tanh_fast(float x) {
    float r; asm("tanh.approx.f32 %0, %1;" : "=f"(r) : "f"(x)); return r;
}
__device__ __forceinline__ void cluster_sync_all() {
    asm volatile("barrier.cluster.arrive.aligned;" ::: "memory");
    asm volatile("barrier.cluster.wait.aligned;" ::: "memory");
}
__device__ __forceinline__ void mbar_init(unsigned a, unsigned cnt) {
    asm volatile("mbarrier.init.shared.b64 [%0], %1;" :: "r"(a), "r"(cnt) : "memory");
}
__device__ __forceinline__ void mbar_expect(unsigned a, unsigned bytes) {
    asm volatile("mbarrier.arrive.expect_tx.shared.b64 _, [%0], %1;"
                 :: "r"(a), "r"(bytes) : "memory");
}
__device__ __forceinline__ void mbar_wait(unsigned a, unsigned parity) {
    asm volatile(
        "{\n\t.reg .pred P;\n\t"
        "LW_%=:\n\t"
        "mbarrier.try_wait.parity.acquire.cluster.shared::cta.b64 P, [%0], %1, 0x989680;\n\t"
        "@P bra.uni LD_%=;\n\t"
        "bra.uni LW_%=;\n\t"
        "LD_%=:\n\t}"
        :: "r"(a), "r"(parity) : "memory");
}
__device__ __forceinline__ void st_async_pre(unsigned ra, unsigned rb, unsigned val) {
    asm volatile(
        "st.async.shared::cluster.mbarrier::complete_tx::bytes.b32 [%0], %1, [%2];"
        :: "r"(ra), "r"(val), "r"(rb) : "memory");
}

// ---------------------------------------------------------------------------
// GEMM1: visit[t][d] = sum_k H[k][t] * X[k][d]
//   128x64 tile, 256 threads, 8x4 per thread (f32x2-packed along m) — R4 config
// ---------------------------------------------------------------------------
__global__ void __launch_bounds__(256)
gemm1_kernel(const float* __restrict__ H, const float* __restrict__ X)
{
    __shared__ float As[16 * 128];
    __shared__ float Bs[16 * 64];
    const int tid = threadIdx.x;
    const int t0 = blockIdx.x * 128;
    const int d0 = blockIdx.y * 64;
    const int tx = tid & 15;
    const int ty = tid >> 4;

    ull acc2[4][4];
#pragma unroll
    for (int mp = 0; mp < 4; mp++)
#pragma unroll
        for (int n = 0; n < 4; n++) acc2[mp][n] = 0ull;

    for (int k0 = 0; k0 < N_CODES; k0 += 16) {
#pragma unroll
        for (int j = 0; j < 2; j++) {
            int idx = tid + (j << 8);
            int kk  = idx >> 5;
            int tt4 = (idx & 31) << 2;
            float4 v = *(const float4*)(H + (size_t)(k0 + kk) * T_STEPS + t0 + tt4);
            *(float4*)(As + (kk << 7) + tt4) = v;
        }
        {
            int kk  = tid >> 4;
            int dd4 = (tid & 15) << 2;
            float4 v = *(const float4*)(X + (size_t)(k0 + kk) * VDIM + d0 + dd4);
            *(float4*)(Bs + (kk << 6) + dd4) = v;
        }
        __syncthreads();
#pragma unroll
        for (int kk = 0; kk < 16; kk++) {
            const longlong2* ap = (const longlong2*)(As + (kk << 7) + (ty << 3));
            longlong2 a01 = ap[0];
            longlong2 a23 = ap[1];
            ull am[4] = {(ull)a01.x, (ull)a01.y, (ull)a23.x, (ull)a23.y};
            float4 b = *(const float4*)(Bs + (kk << 6) + (tx << 2));
            ull bd[4] = {pk2dup(b.x), pk2dup(b.y), pk2dup(b.z), pk2dup(b.w)};
#pragma unroll
            for (int mp = 0; mp < 4; mp++)
#pragma unroll
                for (int n = 0; n < 4; n++)
                    fma2(acc2[mp][n], am[mp], bd[n]);
        }
        __syncthreads();
    }
#pragma unroll
    for (int mp = 0; mp < 4; mp++) {
        float2 c0 = upk2(acc2[mp][0]);
        float2 c1 = upk2(acc2[mp][1]);
        float2 c2 = upk2(acc2[mp][2]);
        float2 c3 = upk2(acc2[mp][3]);
        size_t r0 = (size_t)(t0 + (ty << 3) + 2 * mp) * VDIM + d0 + (tx << 2);
        *(float4*)(g_visit + r0)        = make_float4(c0.x, c1.x, c2.x, c3.x);
        *(float4*)(g_visit + r0 + VDIM) = make_float4(c0.y, c1.y, c2.y, c3.y);
    }
}

// ---------------------------------------------------------------------------
// GEMM2: gi[t][g] = b_ih[g] + sum_d visit[t][d] * W_ih[g][d]  — R4 config
// ---------------------------------------------------------------------------
__global__ void __launch_bounds__(256)
gemm2_kernel(const float* __restrict__ Wih, const float* __restrict__ bih)
{
    __shared__ float As[16 * 128];
    __shared__ float Bs[16 * 64];
    const int tid = threadIdx.x;
    const int t0 = blockIdx.x * 128;
    const int g0 = blockIdx.y * 64;
    const int tx = tid & 15;
    const int ty = tid >> 4;

    ull acc2[4][4];
#pragma unroll
    for (int mp = 0; mp < 4; mp++)
#pragma unroll
        for (int n = 0; n < 4; n++) acc2[mp][n] = 0ull;

    for (int k0 = 0; k0 < VDIM; k0 += 16) {
#pragma unroll
        for (int j = 0; j < 2; j++) {
            int idx = tid + (j << 8);
            int tt  = idx >> 2;
            int kk  = (idx & 3) << 2;
            float4 v = *(const float4*)(g_visit + (size_t)(t0 + tt) * VDIM + k0 + kk);
            As[(kk + 0) * 128 + tt] = v.x;
            As[(kk + 1) * 128 + tt] = v.y;
            As[(kk + 2) * 128 + tt] = v.z;
            As[(kk + 3) * 128 + tt] = v.w;
        }
        {
            int gg = tid >> 2;
            int kk = (tid & 3) << 2;
            float4 v = *(const float4*)(Wih + (size_t)(g0 + gg) * VDIM + k0 + kk);
            Bs[(kk + 0) * 64 + gg] = v.x;
            Bs[(kk + 1) * 64 + gg] = v.y;
            Bs[(kk + 2) * 64 + gg] = v.z;
            Bs[(kk + 3) * 64 + gg] = v.w;
        }
        __syncthreads();
#pragma unroll
        for (int kk = 0; kk < 16; kk++) {
            const longlong2* ap = (const longlong2*)(As + (kk << 7) + (ty << 3));
            longlong2 a01 = ap[0];
            longlong2 a23 = ap[1];
            ull am[4] = {(ull)a01.x, (ull)a01.y, (ull)a23.x, (ull)a23.y};
            float4 b = *(const float4*)(Bs + (kk << 6) + (tx << 2));
            ull bd[4] = {pk2dup(b.x), pk2dup(b.y), pk2dup(b.z), pk2dup(b.w)};
#pragma unroll
            for (int mp = 0; mp < 4; mp++)
#pragma unroll
                for (int n = 0; n < 4; n++)
                    fma2(acc2[mp][n], am[mp], bd[n]);
        }
        __syncthreads();
    }
    float4 bv = *(const float4*)(bih + g0 + (tx << 2));
#pragma unroll
    for (int mp = 0; mp < 4; mp++) {
        float2 c0 = upk2(acc2[mp][0]);
        float2 c1 = upk2(acc2[mp][1]);
        float2 c2 = upk2(acc2[mp][2]);
        float2 c3 = upk2(acc2[mp][3]);
        size_t r0 = (size_t)(t0 + (ty << 3) + 2 * mp) * G3 + g0 + (tx << 2);
        *(float4*)(g_gi + r0)      = make_float4(c0.x + bv.x, c1.x + bv.y, c2.x + bv.z, c3.x + bv.w);
        *(float4*)(g_gi + r0 + G3) = make_float4(c0.y + bv.x, c1.y + bv.y, c2.y + bv.z, c3.y + bv.w);
    }
}

// ---------------------------------------------------------------------------
// GRU scan: 16-CTA cluster, 256 threads (8 warps), BAR-FREE loop
// (mbarrier + st.async recurrence). ALL 6 weight groups in registers
// (192 regs W + 32 regs h) — zero weight smem traffic per step.
// ---------------------------------------------------------------------------
#define SCAN_THREADS 256

__global__ void __launch_bounds__(SCAN_THREADS, 1)
scan_kernel(const float* __restrict__ Whh, const float* __restrict__ bhh)
{
    __shared__ float  hT[2 * HD];         // transposed h, 2 buffers
    __shared__ ull    mbar[2];

    const int tid  = threadIdx.x;
    const int lane = tid & 31;
    const int w    = tid >> 5;
    const int cta  = blockIdx.x;          // cluster rank
    const int c4   = lane & 15;           // h-chunk (source CTA) index
    const int rh   = lane >> 4;

    const int ui    = ((lane & 1) << 1) | rh;
    const int q     = (lane >> 1) & 7;
    const int ul    = (w << 2) + ui;
    const int u_gbl = (cta << 5) + ul;

    // --- one-time weight staging: all 6 groups in registers ---
    // row(g): gate = g>>1, unit-low = ((g&1)<<1)+rh
    ull wreg[6][16];
#pragma unroll
    for (int g = 0; g < 6; g++) {
        int grow = ((g >> 1) << 9) + (cta << 5) + (w << 2) + ((g & 1) << 1) + rh;
        const ull* src = (const ull*)(Whh + (size_t)grow * HD + (c4 << 5));
#pragma unroll
        for (int k = 0; k < 16; k++) wreg[g][k] = src[k];
    }
    const float br = bhh[u_gbl];
    const float bz = bhh[HD + u_gbl];
    const float bn = bhh[2 * HD + u_gbl];

    for (int i = tid; i < HD; i += SCAN_THREADS) hT[i] = 0.0f;
    if (tid == 0) { mbar_init(smem_u32(&mbar[0]), 1); mbar_init(smem_u32(&mbar[1]), 1); }
    __syncthreads();
    cluster_sync_all();

    // precompute remote addresses (2 ranks x 2 buffers)
    const int hoffb = ((ul >> 2) << 6) + (cta << 2) + (ul & 3);
    unsigned rdata[2][2], rbar[2][2];
#pragma unroll
    for (int b = 0; b < 2; b++) {
        unsigned ld = smem_u32(&hT[(b << 9) + hoffb]);
        unsigned lm = smem_u32(&mbar[b]);
#pragma unroll
        for (int r = 0; r < 2; r++) {
            rdata[b][r] = mapa_u32(ld, (q << 1) + r);
            rbar[b][r]  = mapa_u32(lm, (q << 1) + r);
        }
    }

    // gi preload for t=0; carried pointer (no per-step t*G3 multiply)
    const float* gp_cur = g_gi + u_gbl;
    float gir = __ldg(gp_cur);
    float giz = __ldg(gp_cur + HD);
    float gin = __ldg(gp_cur + 2 * HD);

    int ph0 = 0, ph1 = 0;
    const bool b0 = (lane & 1);
    for (int t = 0; t < T_STEPS; t++) {
        const int cb = t & 1;
        const int nb = cb ^ 1;

        if (tid == 0) mbar_expect(smem_u32(&mbar[nb]), 2048u);

        // prefetch gi for t+1 (carried pointer)
        const float* gp_n = (t + 1 < T_STEPS) ? (gp_cur + G3) : gp_cur;
        float girn = __ldg(gp_n);
        float gizn = __ldg(gp_n + HD);
        float ginn = __ldg(gp_n + 2 * HD);
        gp_cur = gp_n;

        // load h chunk (32 floats) — transposed layout, conflict-free
        ull h2[16];
        {
            const longlong2* hp = (const longlong2*)(hT + (cb << 9));
#pragma unroll
            for (int j = 0; j < 8; j++) {
                longlong2 qv = hp[(j << 4) + c4];
                h2[2 * j]     = (ull)qv.x;
                h2[2 * j + 1] = (ull)qv.y;
            }
        }
        float hold = hT[(cb << 9) + hoffb];

        // matvec: 6 groups, all from registers
        float accs[6];
#pragma unroll
        for (int g = 0; g < 6; g++) {
            ull a = 0ull;
#pragma unroll
            for (int k = 0; k < 16; k++) fma2(a, wreg[g][k], h2[k]);
            float2 u2 = upk2(a);
            accs[g] = u2.x + u2.y;
        }

        // xor butterfly levels 8,4,2
#pragma unroll
        for (int d = 8; d > 1; d >>= 1)
#pragma unroll
            for (int g = 0; g < 6; g++)
                accs[g] += __shfl_xor_sync(0xffffffffu, accs[g], d);

        // level 1 with partner-swap: send the partial the partner needs
        float v0 = b0 ? accs[0] : accs[1];
        float v1 = b0 ? accs[2] : accs[3];
        float v2 = b0 ? accs[4] : accs[5];
        float pr = (b0 ? accs[1] : accs[0]) + __shfl_xor_sync(0xffffffffu, v0, 1);
        float pz = (b0 ? accs[3] : accs[2]) + __shfl_xor_sync(0xffffffffu, v1, 1);
        float pn = (b0 ? accs[5] : accs[4]) + __shfl_xor_sync(0xffffffffu, v2, 1);

        float rg = fmaf(0.5f, tanh_fast(0.5f * (gir + pr + br)), 0.5f);
        float zg = fmaf(0.5f, tanh_fast(0.5f * (giz + pz + bz)), 0.5f);
        float ng = tanh_fast(fmaf(rg, pn + bn, gin));
        float hnew = fmaf(zg, hold - ng, ng);

        if (q == 0) g_hs[(size_t)t * HD + u_gbl] = hnew;

        unsigned hv = __float_as_uint(hnew);
        st_async_pre(rdata[nb][0], rbar[nb][0], hv);
        st_async_pre(rdata[nb][1], rbar[nb][1], hv);

        gir = girn; giz = gizn; gin = ginn;

        unsigned par = nb ? (unsigned)ph1 : (unsigned)ph0;
        mbar_wait(smem_u32(&mbar[nb]), par);
        if (nb) ph1 ^= 1; else ph0 ^= 1;
    }
    cluster_sync_all();
}

// ---------------------------------------------------------------------------
// Attention pooling
// ---------------------------------------------------------------------------
__global__ void __launch_bounds__(128)
att_logits_kernel(const float* __restrict__ watt)
{
    int w = blockIdx.x * 4 + (threadIdx.x >> 5);
    int lane = threadIdx.x & 31;
    for (int i = 0; i < 8; i++) {
        int t = w * 8 + i;
        const float* hp = g_hs + (size_t)t * HD;
        float acc = 0.f;
#pragma unroll
        for (int k = 0; k < 16; k++)
            acc += hp[lane + (k << 5)] * watt[lane + (k << 5)];
        acc += __shfl_xor_sync(0xffffffffu, acc, 16);
        acc += __shfl_xor_sync(0xffffffffu, acc, 8);
        acc += __shfl_xor_sync(0xffffffffu, acc, 4);
        acc += __shfl_xor_sync(0xffffffffu, acc, 2);
        acc += __shfl_xor_sync(0xffffffffu, acc, 1);
        if (lane == 0) g_logits[t] = acc;
    }
}

__global__ void __launch_bounds__(1024)
att_softmax_kernel()
{
    __shared__ float red[1024];
    int tid = threadIdx.x;
    float l[4];
    float mx = -1e30f;
#pragma unroll
    for (int i = 0; i < 4; i++) {
        l[i] = g_logits[tid + (i << 10)];
        mx = fmaxf(mx, l[i]);
    }
    red[tid] = mx;
    __syncthreads();
    for (int s = 512; s > 0; s >>= 1) {
        if (tid < s) red[tid] = fmaxf(red[tid], red[tid + s]);
        __syncthreads();
    }
    mx = red[0];
    __syncthreads();
    float e[4];
    float se = 0.f;
#pragma unroll
    for (int i = 0; i < 4; i++) {
        e[i] = __expf(l[i] - mx);
        se += e[i];
    }
    red[tid] = se;
    __syncthreads();
    for (int s = 512; s > 0; s >>= 1) {
        if (tid < s) red[tid] += red[tid + s];
        __syncthreads();
    }
    float inv = 1.0f / red[0];
#pragma unroll
    for (int i = 0; i < 4; i++)
        g_alpha[tid + (i << 10)] = e[i] * inv;
}

__global__ void __launch_bounds__(512)
att_out_kernel()
{
    int b = blockIdx.x;
    int d = threadIdx.x;
    float acc = 0.f;
    for (int i = 0; i < 128; i++) {
        int t = b * 128 + i;
        acc += g_alpha[t] * g_hs[(size_t)t * HD + d];
    }
    g_part[b * HD + d] = acc;
}

__global__ void __launch_bounds__(512)
att_final_kernel(float* __restrict__ out)
{
    int d = threadIdx.x;
    float acc = 0.f;
#pragma unroll
    for (int b = 0; b < 32; b++)
        acc += g_part[b * HD + d];
    out[d] = acc;
}

// ---------------------------------------------------------------------------
// Launch — single stream (proven structure)
// ---------------------------------------------------------------------------
extern "C" void kernel_launch(void* const* d_in, const int* in_sizes, int n_in,
                              void* d_out, int out_size)
{
    const float* H    = (const float*)d_in[0];
    // d_in[1] = TE (unused by reference)
    const float* X    = (const float*)d_in[2];
    const float* Wih  = (const float*)d_in[3];
    const float* Whh  = (const float*)d_in[4];
    const float* bih  = (const float*)d_in[5];
    const float* bhh  = (const float*)d_in[6];
    const float* watt = (const float*)d_in[7];
    float* out = (float*)d_out;

    gemm1_kernel<<<dim3(32, 8), 256>>>(H, X);
    gemm2_kernel<<<dim3(32, 24), 256>>>(Wih, bih);

    cudaFuncSetAttribute(scan_kernel,
                         cudaFuncAttributeNonPortableClusterSizeAllowed, 1);

    cudaLaunchConfig_t cfg = {};
    cfg.gridDim = dim3(16, 1, 1);
    cfg.blockDim = dim3(SCAN_THREADS, 1, 1);
    cfg.dynamicSmemBytes = 0;
    cfg.stream = 0;
    cudaLaunchAttribute attr[1];
    attr[0].id = cudaLaunchAttributeClusterDimension;
    attr[0].val.clusterDim.x = 16;
    attr[0].val.clusterDim.y = 1;
    attr[0].val.clusterDim.z = 1;
    cfg.attrs = attr;
    cfg.numAttrs = 1;
    cudaLaunchKernelEx(&cfg, scan_kernel, Whh, bhh);

    att_logits_kernel<<<128, 128>>>(watt);
    att_softmax_kernel<<<1, 1024>>>();
    att_out_kernel<<<32, 512>>>();
    att_final_kernel<<<1, 512>>>(out);
}